// round 13
// baseline (speedup 1.0000x reference)
#include <cuda_runtime.h>
#include <cuda_pipeline.h>

#define NROWS 524288
#define DDIM  256
#define NSEG  128
#define WARPS 8
#define ROWS_PER_TILE 64                    // 8 warps * 8 rows
#define NTILES (NROWS / ROWS_PER_TILE)      // 8192
#define GRID   888                          // 148 SMs * 6 blocks = one wave
#define RING   4

// ---------------- scratch (device globals; no allocation) ----------------
__device__ __align__(16) float g_u[DDIM];   // Wk @ ones
__device__ __align__(16) float g_v[DDIM];   // Wv @ Wo
__device__ float    g_num[NSEG];
__device__ float    g_den[NSEG];
__device__ unsigned g_done;                 // completion ticket

// ---------------- kernel 0: weight collapse + accumulator init ----------------
__global__ void __launch_bounds__(256) prep_kernel(const float* __restrict__ Wk,
                                                   const float* __restrict__ Wv,
                                                   const float* __restrict__ Wo) {
    __shared__ float swo[DDIM];
    int t = threadIdx.x;
    swo[t] = Wo[t];

    if (blockIdx.x == 0) {
        if (t < NSEG) { g_num[t] = 0.0f; g_den[t] = 0.0f; }
        if (t == 128) g_done = 0u;
    }
    __syncthreads();

    int lane = t & 31;
    int warp = t >> 5;
    int d = blockIdx.x * 8 + warp;

    const float4* wk = reinterpret_cast<const float4*>(Wk + (size_t)d * DDIM);
    const float4* wv = reinterpret_cast<const float4*>(Wv + (size_t)d * DDIM);
    const float4* wo = reinterpret_cast<const float4*>(swo);

    float su = 0.0f, sv = 0.0f;
#pragma unroll
    for (int i = 0; i < 2; i++) {
        int idx = lane + 32 * i;
        float4 k = wk[idx];
        float4 v = wv[idx];
        float4 o = wo[idx];
        su += (k.x + k.y) + (k.z + k.w);
        sv += v.x * o.x + v.y * o.y + v.z * o.z + v.w * o.w;
    }
#pragma unroll
    for (int o = 16; o > 0; o >>= 1) {
        su += __shfl_down_sync(0xFFFFFFFFu, su, o);
        sv += __shfl_down_sync(0xFFFFFFFFu, sv, o);
    }
    if (lane == 0) { g_u[d] = su; g_v[d] = sv; }
}

// ---------------- tile-persistent fused kernel --------------------------------
// One wave of 888 blocks. Each block processes 64-row tiles stride-888.
// Inner loop = R10's proven 8-row depth-3 cp.async ring, unchanged, except
// iterations 5..7 prefetch the NEXT tile's rows 0..2 (pipeline handover) --
// the ring never drains until the block's final tile. Slot arithmetic stays
// globally consistent because 8 % RING == 0.
__global__ void __launch_bounds__(256, 6)
fused_kernel(const float* __restrict__ x, const int* __restrict__ seg,
             const float* __restrict__ bv, const float* __restrict__ Wo,
             const float* __restrict__ bo, float* __restrict__ out)
{
    __shared__ __align__(16) float4 ring[WARPS][RING][DDIM / 4];  // 32 KB
    __shared__ float s_num[NSEG];
    __shared__ float s_den[NSEG];
    __shared__ bool  s_last;

    int t    = threadIdx.x;
    int lane = t & 31;
    int warp = t >> 5;

    if (t < NSEG) { s_num[t] = 0.0f; s_den[t] = 0.0f; }
    __syncthreads();

    // weights in registers: chunks lane and lane+32 (matches copied chunks)
    const float4* gu4 = reinterpret_cast<const float4*>(g_u);
    const float4* gv4 = reinterpret_cast<const float4*>(g_v);
    float4 ua = gu4[lane], ub = gu4[32 + lane];
    float4 va = gv4[lane], vb = gv4[32 + lane];

    const float4* x4 = reinterpret_cast<const float4*>(x);

    int tile = blockIdx.x;

    // prologue: first tile's rows 0..2 in flight (slots 0..2)
    {
        int row0 = tile * ROWS_PER_TILE + warp * 8;
#pragma unroll
        for (int r = 0; r < 3; r++) {
            const float4* src = x4 + (size_t)(row0 + r) * (DDIM / 4);
            float4* dst = &ring[warp][r][0];
            __pipeline_memcpy_async(dst + lane,      src + lane,      16);
            __pipeline_memcpy_async(dst + lane + 32, src + lane + 32, 16);
            __pipeline_commit();
        }
    }

    float accN = 0.0f, accD = 0.0f;
    int curSeg = -1;

    for (;;) {
        int nextTile = tile + GRID;
        bool hasNext = nextTile < NTILES;
        int row0  = tile * ROWS_PER_TILE + warp * 8;
        int nrow0 = nextTile * ROWS_PER_TILE + warp * 8;

#pragma unroll
        for (int r = 0; r < 8; r++) {
            // prefetch row r+3 of the warp's global row sequence
            if (r < 5) {
                const float4* src = x4 + (size_t)(row0 + r + 3) * (DDIM / 4);
                float4* dst = &ring[warp][(r + 3) & (RING - 1)][0];
                __pipeline_memcpy_async(dst + lane,      src + lane,      16);
                __pipeline_memcpy_async(dst + lane + 32, src + lane + 32, 16);
            } else if (hasNext) {            // handover: next tile rows 0..2
                const float4* src = x4 + (size_t)(nrow0 + r - 5) * (DDIM / 4);
                float4* dst = &ring[warp][(r + 3) & (RING - 1)][0];
                __pipeline_memcpy_async(dst + lane,      src + lane,      16);
                __pipeline_memcpy_async(dst + lane + 32, src + lane + 32, 16);
            }
            __pipeline_commit();             // empty group at the very end: instant
            __pipeline_wait_prior(3);        // row r of this tile landed

            const float4* slot = &ring[warp][r & (RING - 1)][0];
            float4 x0 = slot[lane];
            float4 x1 = slot[lane + 32];

            float lg, vl;
            lg = x0.x * ua.x;           vl = x0.x * va.x;
            lg = fmaf(x0.y, ua.y, lg);  vl = fmaf(x0.y, va.y, vl);
            lg = fmaf(x0.z, ua.z, lg);  vl = fmaf(x0.z, va.z, vl);
            lg = fmaf(x0.w, ua.w, lg);  vl = fmaf(x0.w, va.w, vl);
            lg = fmaf(x1.x, ub.x, lg);  vl = fmaf(x1.x, vb.x, vl);
            lg = fmaf(x1.y, ub.y, lg);  vl = fmaf(x1.y, vb.y, vl);
            lg = fmaf(x1.z, ub.z, lg);  vl = fmaf(x1.z, vb.z, vl);
            lg = fmaf(x1.w, ub.w, lg);  vl = fmaf(x1.w, vb.w, vl);

#pragma unroll
            for (int o = 16; o > 0; o >>= 1) {
                lg += __shfl_down_sync(0xFFFFFFFFu, lg, o);
                vl += __shfl_down_sync(0xFFFFFFFFu, vl, o);
            }

            if (lane == 0) {
                int s = __ldg(&seg[row0 + r]);
                if (s != curSeg) {           // sorted segments: rare
                    if (curSeg >= 0) {
                        atomicAdd(&s_num[curSeg], accN);
                        atomicAdd(&s_den[curSeg], accD);
                    }
                    curSeg = s; accN = 0.0f; accD = 0.0f;
                }
                float e = __expf(lg);
                accD += e;
                accN = fmaf(e, vl, accN);
            }
        }

        if (!hasNext) break;
        tile = nextTile;
    }

    if (lane == 0 && curSeg >= 0) {
        atomicAdd(&s_num[curSeg], accN);
        atomicAdd(&s_den[curSeg], accD);
    }

    __syncthreads();
    if (t < NSEG && s_den[t] != 0.0f) {
        atomicAdd(&g_num[t], s_num[t]);
        atomicAdd(&g_den[t], s_den[t]);
    }

    // ---- last-block fused finalize ----
    __threadfence();
    __syncthreads();
    if (t == 0) {
        unsigned ticket = atomicAdd(&g_done, 1u);
        s_last = (ticket == (unsigned)(gridDim.x - 1));
    }
    __syncthreads();
    if (!s_last) return;

    __shared__ float s_red[256];
    s_red[t] = bv[t] * Wo[t];
    __syncthreads();
#pragma unroll
    for (int o = 128; o > 0; o >>= 1) {
        if (t < o) s_red[t] += s_red[t + o];
        __syncthreads();
    }
    float c2 = s_red[0];
    float b  = bo[0];
    if (t < NSEG) {
        float den = g_den[t];
        out[t] = (den != 0.0f) ? (g_num[t] / den + c2 + b) : b;
    }
}

// ---------------- launch ----------------
extern "C" void kernel_launch(void* const* d_in, const int* in_sizes, int n_in,
                              void* d_out, int out_size) {
    const float* x   = (const float*)d_in[0];
    const int*   seg = (const int*)d_in[1];
    const float* Wk  = (const float*)d_in[2];
    // d_in[3] = bk (cancels in the segment softmax; unused)
    const float* Wv  = (const float*)d_in[4];
    const float* bv  = (const float*)d_in[5];
    const float* Wo  = (const float*)d_in[6];
    const float* bo  = (const float*)d_in[7];
    float* out = (float*)d_out;

    prep_kernel<<<32, 256>>>(Wk, Wv, Wo);
    fused_kernel<<<GRID, 256>>>(x, seg, bv, Wo, bo, out);
}

// round 14
// speedup vs baseline: 1.0898x; 1.0898x over previous
#include <cuda_runtime.h>
#include <cuda_pipeline.h>

#define NROWS 524288
#define DDIM  256
#define NSEG  128
#define WARPS 8
#define ROWS_PER_WARP 8
#define ROWS_PER_BLOCK (WARPS * ROWS_PER_WARP)      // 64
#define GRID  (NROWS / ROWS_PER_BLOCK)              // 8192
#define RING  4                                     // rows buffered per warp

// ---------------- scratch (device globals; no allocation) ----------------
__device__ __align__(16) float g_u[DDIM];   // Wk @ ones
__device__ __align__(16) float g_v[DDIM];   // Wv @ Wo
__device__ float    g_num[NSEG];
__device__ float    g_den[NSEG];
__device__ unsigned g_done;                 // completion ticket

// ---------------- kernel 0: weight collapse + accumulator init ----------------
// Triggers programmatic launch completion immediately after the (fenced)
// weight writes, so the fused kernel's blocks can begin their cp.async
// prologue while this kernel drains.
__global__ void __launch_bounds__(256) prep_kernel(const float* __restrict__ Wk,
                                                   const float* __restrict__ Wv,
                                                   const float* __restrict__ Wo) {
    __shared__ float swo[DDIM];
    int t = threadIdx.x;
    swo[t] = Wo[t];

    if (blockIdx.x == 0) {
        if (t < NSEG) { g_num[t] = 0.0f; g_den[t] = 0.0f; }
        if (t == 128) g_done = 0u;
    }
    __syncthreads();

    int lane = t & 31;
    int warp = t >> 5;
    int d = blockIdx.x * 8 + warp;

    const float4* wk = reinterpret_cast<const float4*>(Wk + (size_t)d * DDIM);
    const float4* wv = reinterpret_cast<const float4*>(Wv + (size_t)d * DDIM);
    const float4* wo = reinterpret_cast<const float4*>(swo);

    float su = 0.0f, sv = 0.0f;
#pragma unroll
    for (int i = 0; i < 2; i++) {
        int idx = lane + 32 * i;
        float4 k = wk[idx];
        float4 v = wv[idx];
        float4 o = wo[idx];
        su += (k.x + k.y) + (k.z + k.w);
        sv += v.x * o.x + v.y * o.y + v.z * o.z + v.w * o.w;
    }
#pragma unroll
    for (int o = 16; o > 0; o >>= 1) {
        su += __shfl_down_sync(0xFFFFFFFFu, su, o);
        sv += __shfl_down_sync(0xFFFFFFFFu, sv, o);
    }
    if (lane == 0) { g_u[d] = su; g_v[d] = sv; }

    // publish writes, then allow the dependent kernel to start
    __syncthreads();
    if (t == 0) __threadfence();
    __syncthreads();
    cudaTriggerProgrammaticLaunchCompletion();
}

// ---------------- fused kernel: per-warp cp.async ring (R10, frozen) ----------
// Each warp owns 8 consecutive rows and a private 4-row (4KB) smem ring;
// depth-3 cp.async pipeline, weights in registers, register segment-carry.
// PDL: the cp.async prologue is weight-independent, so it issues BEFORE
// cudaGridDependencySynchronize(); the prep tail hides under the ramp.
__global__ void __launch_bounds__(256, 6)
fused_kernel(const float* __restrict__ x, const int* __restrict__ seg,
             const float* __restrict__ bv, const float* __restrict__ Wo,
             const float* __restrict__ bo, float* __restrict__ out)
{
    __shared__ __align__(16) float4 ring[WARPS][RING][DDIM / 4];  // 32 KB
    __shared__ float s_num[NSEG];
    __shared__ float s_den[NSEG];
    __shared__ bool  s_last;

    int t    = threadIdx.x;
    int lane = t & 31;
    int warp = t >> 5;

    if (t < NSEG) { s_num[t] = 0.0f; s_den[t] = 0.0f; }

    int row0 = blockIdx.x * ROWS_PER_BLOCK + warp * ROWS_PER_WARP;
    const float4* x4 = reinterpret_cast<const float4*>(x);

    // prologue: rows 0..2 in flight (weight-independent; overlaps prep tail)
#pragma unroll
    for (int r = 0; r < 3; r++) {
        const float4* src = x4 + (size_t)(row0 + r) * (DDIM / 4);
        float4* dst = &ring[warp][r & (RING - 1)][0];
        __pipeline_memcpy_async(dst + lane,      src + lane,      16);
        __pipeline_memcpy_async(dst + lane + 32, src + lane + 32, 16);
        __pipeline_commit();
    }

    // wait for prep's weight writes to be visible
    cudaGridDependencySynchronize();

    // weights in registers: chunks lane and lane+32 (matches copied chunks)
    const float4* gu4 = reinterpret_cast<const float4*>(g_u);
    const float4* gv4 = reinterpret_cast<const float4*>(g_v);
    float4 ua = gu4[lane], ub = gu4[32 + lane];
    float4 va = gv4[lane], vb = gv4[32 + lane];

    __syncthreads();   // s_num/s_den published

    float accN = 0.0f, accD = 0.0f;
    int curSeg = -1;

#pragma unroll
    for (int r = 0; r < ROWS_PER_WARP; r++) {
        if (r + 3 < ROWS_PER_WARP) {
            const float4* src = x4 + (size_t)(row0 + r + 3) * (DDIM / 4);
            float4* dst = &ring[warp][(r + 3) & (RING - 1)][0];
            __pipeline_memcpy_async(dst + lane,      src + lane,      16);
            __pipeline_memcpy_async(dst + lane + 32, src + lane + 32, 16);
            __pipeline_commit();
            __pipeline_wait_prior(3);         // row r landed; 3 rows in flight
        } else {
            __pipeline_wait_prior(ROWS_PER_WARP - 1 - r);  // drain tail
        }

        const float4* slot = &ring[warp][r & (RING - 1)][0];
        float4 x0 = slot[lane];
        float4 x1 = slot[lane + 32];

        float lg, vl;
        lg = x0.x * ua.x;           vl = x0.x * va.x;
        lg = fmaf(x0.y, ua.y, lg);  vl = fmaf(x0.y, va.y, vl);
        lg = fmaf(x0.z, ua.z, lg);  vl = fmaf(x0.z, va.z, vl);
        lg = fmaf(x0.w, ua.w, lg);  vl = fmaf(x0.w, va.w, vl);
        lg = fmaf(x1.x, ub.x, lg);  vl = fmaf(x1.x, vb.x, vl);
        lg = fmaf(x1.y, ub.y, lg);  vl = fmaf(x1.y, vb.y, vl);
        lg = fmaf(x1.z, ub.z, lg);  vl = fmaf(x1.z, vb.z, vl);
        lg = fmaf(x1.w, ub.w, lg);  vl = fmaf(x1.w, vb.w, vl);

#pragma unroll
        for (int o = 16; o > 0; o >>= 1) {
            lg += __shfl_down_sync(0xFFFFFFFFu, lg, o);
            vl += __shfl_down_sync(0xFFFFFFFFu, vl, o);
        }

        if (lane == 0) {
            int s = __ldg(&seg[row0 + r]);
            if (s != curSeg) {               // sorted segments: rare
                if (curSeg >= 0) {
                    atomicAdd(&s_num[curSeg], accN);
                    atomicAdd(&s_den[curSeg], accD);
                }
                curSeg = s; accN = 0.0f; accD = 0.0f;
            }
            float e = __expf(lg);
            accD += e;
            accN = fmaf(e, vl, accN);
        }
    }
    if (lane == 0 && curSeg >= 0) {
        atomicAdd(&s_num[curSeg], accN);
        atomicAdd(&s_den[curSeg], accD);
    }

    __syncthreads();
    if (t < NSEG && s_den[t] != 0.0f) {
        atomicAdd(&g_num[t], s_num[t]);
        atomicAdd(&g_den[t], s_den[t]);
    }

    // ---- last-block fused finalize ----
    __threadfence();
    __syncthreads();
    if (t == 0) {
        unsigned ticket = atomicAdd(&g_done, 1u);
        s_last = (ticket == (unsigned)(gridDim.x - 1));
    }
    __syncthreads();
    if (!s_last) return;

    __shared__ float s_red[256];
    s_red[t] = bv[t] * Wo[t];
    __syncthreads();
#pragma unroll
    for (int o = 128; o > 0; o >>= 1) {
        if (t < o) s_red[t] += s_red[t + o];
        __syncthreads();
    }
    float c2 = s_red[0];
    float b  = bo[0];
    if (t < NSEG) {
        float den = g_den[t];
        out[t] = (den != 0.0f) ? (g_num[t] / den + c2 + b) : b;
    }
}

// ---------------- launch ----------------
extern "C" void kernel_launch(void* const* d_in, const int* in_sizes, int n_in,
                              void* d_out, int out_size) {
    const float* x   = (const float*)d_in[0];
    const int*   seg = (const int*)d_in[1];
    const float* Wk  = (const float*)d_in[2];
    // d_in[3] = bk (cancels in the segment softmax; unused)
    const float* Wv  = (const float*)d_in[4];
    const float* bv  = (const float*)d_in[5];
    const float* Wo  = (const float*)d_in[6];
    const float* bo  = (const float*)d_in[7];
    float* out = (float*)d_out;

    prep_kernel<<<32, 256>>>(Wk, Wv, Wo);

    // fused kernel with programmatic dependent launch: its blocks may begin
    // (issuing the weight-independent cp.async prologue) while prep drains.
    cudaLaunchConfig_t cfg = {};
    cfg.gridDim  = dim3(GRID, 1, 1);
    cfg.blockDim = dim3(256, 1, 1);
    cfg.dynamicSmemBytes = 0;
    cfg.stream = 0;
    cudaLaunchAttribute attrs[1];
    attrs[0].id = cudaLaunchAttributeProgrammaticStreamSerialization;
    attrs[0].val.programmaticStreamSerializationAllowed = 1;
    cfg.attrs = attrs;
    cfg.numAttrs = 1;
    cudaLaunchKernelEx(&cfg, fused_kernel, x, seg, bv, Wo, bo, out);
}